// round 11
// baseline (speedup 1.0000x reference)
#include <cuda_runtime.h>

#define FULL 0xffffffffu
#define BNEPS 1e-5f

// ---------------- scratch (device globals; allocation is forbidden) ----------------
__device__ float d_gate[2][64][128][8];   // softmax gates (side, b, t, e)
__device__ float d_y[2][8192][128];       // ungated expert layer-1 outputs [n][e*16+hh]
__device__ float d_hpre[2][8192][16];     // gated expert layer-1 hidden (pre-BN)
__device__ float d_part[2][256][32];      // per-block BN partials [sum(16) | sumsq(16)]
__device__ float d_bn[2][2][16];          // per-side BN scale/shift
__device__ float d_xw0[8192][48];         // precomputed main-GRU layer0 input projection
__device__ float d_Zlast[64][16];         // main GRU final hidden
__device__ float d_q[64][128];            // decoder gated hidden
__device__ unsigned int d_cnt;            // combine completion counter (self-resetting)

// ---------------- fast math ----------------
__device__ __forceinline__ float tanha(float x) {
    float y;
    asm("tanh.approx.f32 %0, %1;" : "=f"(y) : "f"(x));
    return y;
}
__device__ __forceinline__ float sigt(float x) {          // sigmoid via tanh
    return fmaf(tanha(0.5f * x), 0.5f, 0.5f);
}
typedef unsigned long long ull;
__device__ __forceinline__ ull pack2(float x, float y) {
    ull r;
    asm("mov.b64 %0, {%1, %2};" : "=l"(r) : "f"(x), "f"(y));
    return r;
}
__device__ __forceinline__ void unpack2(ull v, float& x, float& y) {
    asm("mov.b64 {%0, %1}, %2;" : "=f"(x), "=f"(y) : "l"(v));
}
__device__ __forceinline__ ull fma2(ull a, ull b, ull c) {
    ull d;
    asm("fma.rn.f32x2 %0, %1, %2, %3;" : "=l"(d) : "l"(a), "l"(b), "l"(c));
    return d;
}
__device__ __forceinline__ ull add2(ull a, ull b) {
    ull d;
    asm("add.rn.f32x2 %0, %1, %2;" : "=l"(d) : "l"(a), "l"(b));
    return d;
}
// packed dot over 8 floats (4 pairs) with packed bias (bias in lo half)
__device__ __forceinline__ float dot8p(const ull* w, const ull* h, ull bias2) {
    ull a0 = fma2(w[0], h[0], bias2);
    ull a1 = fma2(w[1], h[1], 0ull);
    a0 = fma2(w[2], h[2], a0);
    a1 = fma2(w[3], h[3], a1);
    ull s = add2(a0, a1);
    float lo, hi; unpack2(s, lo, hi);
    return lo + hi;
}
// packed dot over 16 floats (8 pairs) with packed bias
__device__ __forceinline__ float dot16p(const ull* w, const ull* h, ull bias2) {
    ull a0 = fma2(w[0], h[0], bias2);
    ull a1 = fma2(w[1], h[1], 0ull);
    a0 = fma2(w[2], h[2], a0);
    a1 = fma2(w[3], h[3], a1);
    a0 = fma2(w[4], h[4], a0);
    a1 = fma2(w[5], h[5], a1);
    a0 = fma2(w[6], h[6], a0);
    a1 = fma2(w[7], h[7], a1);
    ull s = add2(a0, a1);
    float lo, hi; unpack2(s, lo, hi);
    return lo + hi;
}
__device__ __forceinline__ void loadpack(ull* dst, const float* src, int npairs) {
#pragma unroll
    for (int k = 0; k < 8; k++) {
        if (k < npairs) {
            float2 v = *(const float2*)(src + 2 * k);
            dst[k] = pack2(v.x, v.y);
        }
    }
}
__device__ __forceinline__ void lds4(ull* h, const float* hsrc) {
    ulonglong2 q0 = *(const ulonglong2*)hsrc;
    ulonglong2 q1 = *(const ulonglong2*)(hsrc + 4);
    h[0] = q0.x; h[1] = q0.y; h[2] = q1.x; h[3] = q1.y;
}
__device__ __forceinline__ void lds8(ull* h, const float* hsrc) {
    lds4(h, hsrc);
    lds4(h + 4, hsrc + 8);
}

// ---------------- K1 mega: blocks 0-15 = gate GRU (layer-skewed); blocks 16-527 = GEMM ----------------
__global__ void __launch_bounds__(128) mega_kernel(
    const float* __restrict__ Local, const float* __restrict__ Remote,
    const float* __restrict__ Wih0, const float* __restrict__ Whh0,
    const float* __restrict__ bih0, const float* __restrict__ bhh0,
    const float* __restrict__ Wih1, const float* __restrict__ Whh1,
    const float* __restrict__ bih1, const float* __restrict__ bhh1,
    const float* __restrict__ w1, const float* __restrict__ b1)
{
    __shared__ __align__(16) float2 xs2[4][8][128];

    if (blockIdx.x < 16) {
        // ================= gate GRU, pipeline-skewed: L1(t) || L0(t+1) =================
        __shared__ __align__(16) float gb[4][2][2][16];  // [warp][layer][buf][2 sides x 8]
        int w = threadIdx.x >> 5;
        int b = blockIdx.x * 4 + w;                       // 0..63
        int lane = threadIdx.x & 31;
        int sub = (lane >> 3) & 1;                        // lanes 16-31 duplicate 0-15
        int j = lane & 7;
        int r1r = 8 + j, r1n = 16 + j;

        float wir[3], wiz[3], win[3];
#pragma unroll
        for (int k = 0; k < 3; k++) {
            wir[k] = Wih0[j * 3 + k];
            wiz[k] = Wih0[r1r * 3 + k];
            win[k] = Wih0[r1n * 3 + k];
        }
        float bir = bih0[j], biz = bih0[r1r], bin = bih0[r1n];
        ull whr2[4], whz2[4], whn2[4], wir12[4], wiz12[4], win12[4],
            whr12[4], whz12[4], whn12[4];
        loadpack(whr2, Whh0 + j * 8, 4);   loadpack(whz2, Whh0 + r1r * 8, 4);
        loadpack(whn2, Whh0 + r1n * 8, 4);
        loadpack(wir12, Wih1 + j * 8, 4);  loadpack(wiz12, Wih1 + r1r * 8, 4);
        loadpack(win12, Wih1 + r1n * 8, 4);
        loadpack(whr12, Whh1 + j * 8, 4);  loadpack(whz12, Whh1 + r1r * 8, 4);
        loadpack(whn12, Whh1 + r1n * 8, 4);
        ull bhr2 = pack2(bhh0[j], 0.f), bhz2 = pack2(bhh0[r1r], 0.f), bhn2 = pack2(bhh0[r1n], 0.f);
        ull bir12 = pack2(bih1[j], 0.f), biz12 = pack2(bih1[r1r], 0.f), bin12 = pack2(bih1[r1n], 0.f);
        ull bhr12 = pack2(bhh1[j], 0.f), bhz12 = pack2(bhh1[r1r], 0.f), bhn12 = pack2(bhh1[r1n], 0.f);

        ull h0p[4], h1p[4];
#pragma unroll
        for (int k = 0; k < 4; k++) { h0p[k] = 0ull; h1p[k] = 0ull; }
        float own0 = 0.f, own1 = 0.f;

        const float* xb = (sub ? Remote : Local) + (size_t)b * 16896 + 128;
        float* outp = &d_gate[sub][b][0][0];

        // ---- peel: L0 at t=0 (h0 prev = 0) ----
        {
            float4 x0 = *(const float4*)xb;
            float xwr = fmaf(x0.z, wir[2], fmaf(x0.y, wir[1], fmaf(x0.x, wir[0], bir)));
            float xwz = fmaf(x0.z, wiz[2], fmaf(x0.y, wiz[1], fmaf(x0.x, wiz[0], biz)));
            float xwn = fmaf(x0.z, win[2], fmaf(x0.y, win[1], fmaf(x0.x, win[0], bin)));
            float ghr = dot8p(whr2, h0p, bhr2);
            float ghz = dot8p(whz2, h0p, bhz2);
            float ghn = dot8p(whn2, h0p, bhn2);
            float r = sigt(xwr + ghr);
            float z = sigt(xwz + ghz);
            float n = tanha(fmaf(r, ghn, xwn));
            float hn = fmaf(z, own0 - n, n);
            own0 = hn;
            gb[w][0][1][sub * 8 + j] = hn;
            __syncwarp();
            lds4(h0p, &gb[w][0][1][sub * 8]);
        }
        float4 xc = *(const float4*)(xb + 132);     // x(1)

        for (int t = 0; t < 128; t++) {
            int buf = t & 1;
            // ---- L1(t): uses h0p = h0(t), h1p = h1(t-1) ----
            float xwr1 = dot8p(wir12, h0p, bir12);
            float xwz1 = dot8p(wiz12, h0p, biz12);
            float xwn1 = dot8p(win12, h0p, bin12);
            float ghr1 = dot8p(whr12, h1p, bhr12);
            float ghz1 = dot8p(whz12, h1p, bhz12);
            float ghn1 = dot8p(whn12, h1p, bhn12);
            float rr1 = sigt(xwr1 + ghr1);
            float zz1 = sigt(xwz1 + ghz1);
            float nn1 = tanha(fmaf(rr1, ghn1, xwn1));
            float hn1 = fmaf(zz1, own1 - nn1, nn1);
            own1 = hn1;
            // ---- L0(t+1): uses h0p = h0(t), x(t+1) ----
            float xwr0 = fmaf(xc.z, wir[2], fmaf(xc.y, wir[1], fmaf(xc.x, wir[0], bir)));
            float xwz0 = fmaf(xc.z, wiz[2], fmaf(xc.y, wiz[1], fmaf(xc.x, wiz[0], biz)));
            float xwn0 = fmaf(xc.z, win[2], fmaf(xc.y, win[1], fmaf(xc.x, win[0], bin)));
            float ghr0 = dot8p(whr2, h0p, bhr2);
            float ghz0 = dot8p(whz2, h0p, bhz2);
            float ghn0 = dot8p(whn2, h0p, bhn2);
            float r0 = sigt(xwr0 + ghr0);
            float z0 = sigt(xwz0 + ghz0);
            float n0 = tanha(fmaf(r0, ghn0, xwn0));
            float hn0 = fmaf(z0, own0 - n0, n0);
            own0 = hn0;
            // ---- combined broadcast ----
            gb[w][1][buf][sub * 8 + j] = hn1;
            gb[w][0][buf][sub * 8 + j] = hn0;
            __syncwarp();
            lds4(h1p, &gb[w][1][buf][sub * 8]);
            lds4(h0p, &gb[w][0][buf][sub * 8]);
            // ---- softmax over 8 (h1 in (-1,1): no max shift) ----
            float ev = __expf(hn1);
            float ss = ev;
            ss += __shfl_xor_sync(FULL, ss, 1);
            ss += __shfl_xor_sync(FULL, ss, 2);
            ss += __shfl_xor_sync(FULL, ss, 4);
            if (lane < 16) outp[t * 8 + j] = __fdividef(ev, ss);
            // ---- prefetch x(t+2) ----
            if (t < 126) xc = *(const float4*)(xb + (size_t)(t + 2) * 132);
        }
    } else {
        // ================= ungated expert layer-1 GEMM =================
        int bx = blockIdx.x - 16;          // 0..511
        int side = bx >> 8;
        int bq = bx & 255;
        const float* src = side ? Remote : Local;
        int w = threadIdx.x >> 5, lane = threadIdx.x & 31;
        int n0 = bq * 32 + w * 8;

#pragma unroll
        for (int s = 0; s < 8; s++) {
            int n = n0 + s;
            int bb = n >> 7, t = n & 127;
            float4 v = *(const float4*)(src + (size_t)bb * 16896 + t * 132 + lane * 4);
            xs2[w][s][lane * 4 + 0] = make_float2(v.x, v.x);
            xs2[w][s][lane * 4 + 1] = make_float2(v.y, v.y);
            xs2[w][s][lane * 4 + 2] = make_float2(v.z, v.z);
            xs2[w][s][lane * 4 + 3] = make_float2(v.w, v.w);
        }
        int e = lane >> 2, hq = lane & 3;
        __syncthreads();

        ull a01[8], a23[8];
#pragma unroll
        for (int s = 0; s < 8; s++) { a01[s] = 0ull; a23[s] = 0ull; }

        const float* wbase = w1 + (size_t)e * 2048 + hq * 4;   // (e*128+i)*16 + 4*hq
#pragma unroll 4
        for (int i = 0; i < 128; i++) {
            float4 wv = *(const float4*)(wbase + i * 16);
            ull w01 = pack2(wv.x, wv.y);
            ull w23 = pack2(wv.z, wv.w);
#pragma unroll
            for (int s = 0; s < 8; s++) {
                ull xp = *(const ull*)&xs2[w][s][i];
                a01[s] = fma2(w01, xp, a01[s]);
                a23[s] = fma2(w23, xp, a23[s]);
            }
        }
        float4 bq4 = *(const float4*)(b1 + e * 16 + hq * 4);
#pragma unroll
        for (int s = 0; s < 8; s++) {
            float v0, v1, v2, v3;
            unpack2(a01[s], v0, v1);
            unpack2(a23[s], v2, v3);
            *(float4*)&d_y[side][n0 + s][lane * 4] =
                make_float4(v0 + bq4.x, v1 + bq4.y, v2 + bq4.z, v3 + bq4.w);
        }
    }
}

// ---------------- K2: gates -> hpre + BN partials; last block finalizes BN ----------------
__global__ void __launch_bounds__(128) combine_kernel(
    const float* __restrict__ ae_g, const float* __restrict__ ae_bt)
{
    __shared__ __align__(16) float ys[32][128];
    __shared__ float gs[32][8];
    __shared__ float hsm[32][16];
    __shared__ float sred[128];
    __shared__ float stot[2][32];
    __shared__ int lastflag;
    int t = threadIdx.x;
    int blk = blockIdx.x;                 // 0..511
    int side = blk >> 8;
    int grp = blk & 255;
    int n0 = grp * 32;
    const float* gp = &d_gate[0][0][0][0];

#pragma unroll
    for (int i = 0; i < 8; i++) {
        int idx = i * 128 + t;            // 1024 float4
        int s = idx >> 5, c = idx & 31;
        ((float4*)&ys[s][0])[c] = ((const float4*)&d_y[side][n0 + s][0])[c];
    }
#pragma unroll
    for (int i = 0; i < 2; i++) {
        int idx = i * 128 + t;            // 256 gates
        int s = idx >> 3, e = idx & 7;
        gs[s][e] = gp[((size_t)side * 8192 + n0 + s) * 8 + e];
    }
    __syncthreads();
    {
        int s = t >> 2, q = t & 3;
        float4 acc = {0.f, 0.f, 0.f, 0.f};
#pragma unroll
        for (int e = 0; e < 8; e++) {
            float g = gs[s][e];
            float4 y4 = *(const float4*)&ys[s][e * 16 + q * 4];
            acc.x = fmaf(g, y4.x, acc.x); acc.y = fmaf(g, y4.y, acc.y);
            acc.z = fmaf(g, y4.z, acc.z); acc.w = fmaf(g, y4.w, acc.w);
        }
        *(float4*)&d_hpre[side][n0 + s][q * 4] = acc;
        *(float4*)&hsm[s][q * 4] = acc;
    }
    __syncthreads();
    if (t < 32) {
        int c = t & 15, kind = t >> 4;
        float a = 0.f;
#pragma unroll 8
        for (int ss = 0; ss < 32; ss++) {
            float v = hsm[ss][c];
            a += kind ? v * v : v;
        }
        d_part[side][grp][t] = a;
    }
    // ---- last-block BN finalize ----
    __threadfence();
    __syncthreads();
    if (t == 0) {
        unsigned int v = atomicAdd(&d_cnt, 1u);
        lastflag = (v == 511u);
    }
    __syncthreads();
    if (lastflag) {
        int sd = t >> 6, rem = t & 63;
        int c = rem & 31, half = rem >> 5;
        float a = 0.f;
#pragma unroll 8
        for (int k = 0; k < 128; k++) a += d_part[sd][half * 128 + k][c];
        sred[t] = a;
        __syncthreads();
        if (t < 64) {
            int s2 = t >> 5, c2 = t & 31;
            stot[s2][c2] = sred[s2 * 64 + c2] + sred[s2 * 64 + 32 + c2];
        }
        __syncthreads();
        if (t < 32) {
            int s2 = t >> 4, ch = t & 15;
            float m = stot[s2][ch] * (1.f / 8192.f);
            float vv = stot[s2][16 + ch] * (1.f / 8192.f) - m * m;
            float a2 = ae_g[ch] * rsqrtf(vv + BNEPS);
            d_bn[s2][0][ch] = a2;
            d_bn[s2][1][ch] = ae_bt[ch] - m * a2;
        }
        if (t == 0) d_cnt = 0u;          // reset for next graph replay
    }
}

// ---------------- K3: fused BN+ELU + gated-combine GEMM + projection ----------------
__global__ void __launch_bounds__(128) fuse2_kernel(
    const float* __restrict__ w2, const float* __restrict__ b2,
    const float* __restrict__ mWih0, const float* __restrict__ mbih0)
{
    __shared__ float sh[32][33];          // ELU'd hidden: [s][0..15]=L, [16..31]=R
    __shared__ __align__(16) float hg[32][132];
    __shared__ __align__(16) float w2t[16][132];   // transposed w2: [o][k]
    __shared__ float b2s[128];
    __shared__ float gl[32][8], gr[32][8];
    __shared__ float zs[32][17];
    __shared__ __align__(16) float mWs[768];
    __shared__ float mbs[48];
    int t = threadIdx.x;
    int n0 = blockIdx.x * 32;
    const float* gp = &d_gate[0][0][0][0];

#pragma unroll
    for (int i = 0; i < 16; i++) {
        int idx = i * 128 + t;           // 2048
        int o = idx >> 7, k = idx & 127;
        w2t[o][k] = w2[k * 16 + o];
    }
    b2s[t] = b2[t];
#pragma unroll
    for (int i = 0; i < 6; i++) mWs[i * 128 + t] = mWih0[i * 128 + t];
    if (t < 48) mbs[t] = mbih0[t];
#pragma unroll
    for (int i = 0; i < 4; i++) {
        int idx = i * 128 + t;           // 512 = 32 samples x 16 gates
        int s = idx >> 4, c = idx & 15;
        float v = gp[((size_t)((c >> 3) * 8192) + n0 + s) * 8 + (c & 7)];
        if (c < 8) gl[s][c] = v; else gr[s][c - 8] = v;
    }
#pragma unroll
    for (int i = 0; i < 8; i++) {
        int idx = i * 128 + t;           // 1024 = 32 x 32
        int s = idx >> 5, c = idx & 31;
        int side = c >> 4, ch = c & 15;
        float a = d_bn[side][0][ch] * d_hpre[side][n0 + s][ch] + d_bn[side][1][ch];
        sh[s][c] = a > 0.f ? a : (__expf(a) - 1.f);
    }
    __syncthreads();
    {
        int e = t >> 4, hh = t & 15;
#pragma unroll 4
        for (int s = 0; s < 32; s++)
            hg[s][t] = fmaf(gl[s][e], sh[s][hh], gr[s][e] * sh[s][16 + hh]);
    }
    __syncthreads();
    {
        int o = t & 15, sg = t >> 4;      // sg 0..7, 4 samples each
        int s0 = sg * 4;
        float a0 = 0.f, a1 = 0.f, a2 = 0.f, a3 = 0.f;
#pragma unroll 4
        for (int k = 0; k < 128; k += 4) {
            float4 wv = *(const float4*)&w2t[o][k];
            float4 g0 = *(const float4*)&hg[s0 + 0][k];
            float4 g1 = *(const float4*)&hg[s0 + 1][k];
            float4 g2 = *(const float4*)&hg[s0 + 2][k];
            float4 g3 = *(const float4*)&hg[s0 + 3][k];
            a0 = fmaf(g0.x, wv.x, a0); a0 = fmaf(g0.y, wv.y, a0);
            a0 = fmaf(g0.z, wv.z, a0); a0 = fmaf(g0.w, wv.w, a0);
            a1 = fmaf(g1.x, wv.x, a1); a1 = fmaf(g1.y, wv.y, a1);
            a1 = fmaf(g1.z, wv.z, a1); a1 = fmaf(g1.w, wv.w, a1);
            a2 = fmaf(g2.x, wv.x, a2); a2 = fmaf(g2.y, wv.y, a2);
            a2 = fmaf(g2.z, wv.z, a2); a2 = fmaf(g2.w, wv.w, a2);
            a3 = fmaf(g3.x, wv.x, a3); a3 = fmaf(g3.y, wv.y, a3);
            a3 = fmaf(g3.z, wv.z, a3); a3 = fmaf(g3.w, wv.w, a3);
        }
        float accs[4] = {a0, a1, a2, a3};
#pragma unroll
        for (int ss = 0; ss < 4; ss++) {
            float bsum = accs[ss];
#pragma unroll
            for (int e = 0; e < 8; e++)
                bsum = fmaf(gl[s0 + ss][e] + gr[s0 + ss][e], b2s[e * 16 + o], bsum);
            zs[s0 + ss][o] = bsum;
        }
    }
    __syncthreads();
    {
        int s = t >> 2, q = t & 3;        // 12 outputs per thread
        float z[16];
#pragma unroll
        for (int h = 0; h < 16; h++) z[h] = zs[s][h];
#pragma unroll
        for (int gi = 0; gi < 12; gi++) {
            int g = q * 12 + gi;
            float acc = mbs[g];
#pragma unroll
            for (int h = 0; h < 16; h++) acc = fmaf(z[h], mWs[g * 16 + h], acc);
            d_xw0[n0 + s][g] = acc;
        }
    }
}

// ---------------- K4: main GRU — pipeline-skewed: L1(t) || L0(t+1); 1 warp/sample ----------------
// lanes 0-15: r+n rows, lanes 16-31: z row
__global__ void __launch_bounds__(32) mgru_kernel(
    const float* __restrict__ Whh0, const float* __restrict__ bhh0_,
    const float* __restrict__ Wih1, const float* __restrict__ bih1_,
    const float* __restrict__ Whh1, const float* __restrict__ bhh1_)
{
    __shared__ __align__(16) float hs[2][2][16];    // [layer][buf][16]
    int b = blockIdx.x;
    int lane = threadIdx.x;
    int j = lane & 15;
    int rowA = (lane < 16) ? j : 16 + j;   // r (lanes<16) or z (lanes>=16)
    int rowB = 32 + j;                     // n row (lanes<16)

    ull whA2[8], whB2[8], wiA12[8], wiB12[8], whA12[8], whB12[8];
    loadpack(whA2, Whh0 + rowA * 16, 8);
    loadpack(whB2, Whh0 + rowB * 16, 8);
    loadpack(wiA12, Wih1 + rowA * 16, 8);
    loadpack(wiB12, Wih1 + rowB * 16, 8);
    loadpack(whA12, Whh1 + rowA * 16, 8);
    loadpack(whB12, Whh1 + rowB * 16, 8);
    ull bhA2 = pack2(bhh0_[rowA], 0.f), bhB2 = pack2(bhh0_[rowB], 0.f);
    ull biA2 = pack2(bih1_[rowA], 0.f), biB2 = pack2(bih1_[rowB], 0.f);
    ull bhA12 = pack2(bhh1_[rowA], 0.f), bhB12 = pack2(bhh1_[rowB], 0.f);

    ull h0p[8], h1p[8];
#pragma unroll
    for (int k = 0; k < 8; k++) { h0p[k] = 0ull; h1p[k] = 0ull; }
    float own0 = 0.f, own1 = 0.f;

    const float* xwp = &d_xw0[b * 128][0];

    // ---- peel: L0 at t=0 (h0 prev = 0) ----
    {
        float xwA0 = xwp[rowA], xwB0 = xwp[rowB];
        float ghA = dot16p(whA2, h0p, bhA2);
        float s = sigt(xwA0 + ghA);
        float ghB = dot16p(whB2, h0p, bhB2);
        float n = tanha(fmaf(s, ghB, xwB0));
        float z = __shfl_sync(FULL, s, 16 + j);
        float hn = fmaf(z, own0 - n, n);
        own0 = hn;
        if (lane < 16) hs[0][1][j] = hn;
        __syncwarp();
        lds8(h0p, &hs[0][1][0]);
    }
    float xwA = xwp[48 + rowA], xwB = xwp[48 + rowB];   // for L0(t=1)

    for (int t = 0; t < 128; t++) {
        int buf = t & 1;
        // ---- L1(t): uses h0p = h0(t), h1p = h1(t-1) ----
        float xwA1 = dot16p(wiA12, h0p, biA2);
        float ghA1 = dot16p(whA12, h1p, bhA12);
        float s1 = sigt(xwA1 + ghA1);
        float xwB1 = dot16p(wiB12, h0p, biB2);
        float ghB1 = dot16p(whB12, h1p, bhB12);
        float n1 = tanha(fmaf(s1, ghB1, xwB1));
        float z1 = __shfl_sync(FULL, s1, 16 + j);
        float hn1 = fmaf(z1, own1 - n1, n1);
        own1 = hn1;
        // ---- L0(t+1): uses h0p = h0(t), xw(t+1) ----
        float ghA0 = dot16p(whA2, h0p, bhA2);
        float s0 = sigt(xwA + ghA0);
        float ghB0 = dot16p(whB2, h0p, bhB2);
        float n0 = tanha(fmaf(s0, ghB0, xwB));
        float z0 = __shfl_sync(FULL, s0, 16 + j);
        float hn0 = fmaf(z0, own0 - n0, n0);
        own0 = hn0;
        // ---- combined broadcast ----
        if (lane < 16) { hs[1][buf][j] = hn1; hs[0][buf][j] = hn0; }
        __syncwarp();
        lds8(h1p, &hs[1][buf][0]);
        lds8(h0p, &hs[0][buf][0]);
        // ---- prefetch xw(t+2) ----
        if (t < 126) { xwA = xwp[(t + 2) * 48 + rowA]; xwB = xwp[(t + 2) * 48 + rowB]; }
    }
    if (lane < 16) d_Zlast[b][j] = own1;
}

// ---------------- K5: decoder expert layer-1 + BN + ELU + gate-weighting ----------------
__global__ void __launch_bounds__(256) dec1_kernel(
    const float* __restrict__ Remote,
    const float* __restrict__ w1, const float* __restrict__ b1,
    const float* __restrict__ gmd, const float* __restrict__ btmd)
{
    __shared__ float w1s[2176];
    __shared__ float sb1[128];
    __shared__ float sh[64][17];
    __shared__ float sa[16], sc[16];
    int tid = threadIdx.x;
    for (int i = tid; i < 2176; i += 256) w1s[i] = w1[i];
    if (tid < 128) sb1[tid] = b1[tid];
    int b = tid >> 2, q = tid & 3;
    float x[17];
#pragma unroll
    for (int k = 0; k < 16; k++) x[k] = d_Zlast[b][k];
    x[16] = Remote[(size_t)b * 16896 + 127 * 132 + 131];
    const float* gp = &d_gate[0][0][0][0];
    float om[8];
#pragma unroll
    for (int e = 0; e < 8; e++) om[e] = gp[(size_t)(8192 + b * 128 + 127) * 8 + e];
    __syncthreads();
    float h[4];
#pragma unroll
    for (int hq = 0; hq < 4; hq++) {
        int hh = q * 4 + hq;
        float acc = 0.f;
#pragma unroll 1
        for (int e = 0; e < 8; e++) {
            float a = sb1[e * 16 + hh];
#pragma unroll
            for (int i = 0; i < 17; i++) a = fmaf(x[i], w1s[e * 272 + i * 16 + hh], a);
            acc = fmaf(om[e], a, acc);
        }
        h[hq] = acc;
        sh[b][hh] = acc;
    }
    __syncthreads();
    if (tid < 16) {
        float s = 0.f, s2 = 0.f;
#pragma unroll 8
        for (int bb = 0; bb < 64; bb++) {
            float v = sh[bb][tid];
            s += v; s2 = fmaf(v, v, s2);
        }
        float m = s * (1.f / 64.f);
        float vv = s2 * (1.f / 64.f) - m * m;
        float a = gmd[tid] * rsqrtf(vv + BNEPS);
        sa[tid] = a;
        sc[tid] = btmd[tid] - m * a;
    }
    __syncthreads();
#pragma unroll
    for (int hq = 0; hq < 4; hq++) {
        int hh = q * 4 + hq;
        float t = sa[hh] * h[hq] + sc[hh];
        float hv = t > 0.f ? t : (__expf(t) - 1.f);
#pragma unroll
        for (int e = 0; e < 8; e++) d_q[b][e * 16 + hh] = om[e] * hv;
    }
}

// ---------------- K6: decoder layer-2 -> output ----------------
__global__ void __launch_bounds__(128) dec2_kernel(
    const float* __restrict__ w2, const float* __restrict__ b2,
    float* __restrict__ out)
{
    int b = blockIdx.x, o = threadIdx.x;
    __shared__ float sq[128];
    sq[o] = d_q[b][o];
    __syncthreads();
    const float* gp = &d_gate[0][0][0][0];
    float acc = 0.f;
#pragma unroll 4
    for (int k = 0; k < 128; k++) acc = fmaf(sq[k], w2[k * 128 + o], acc);
#pragma unroll
    for (int e = 0; e < 8; e++)
        acc = fmaf(gp[(size_t)(8192 + b * 128 + 127) * 8 + e], b2[e * 128 + o], acc);
    out[b * 128 + o] = acc;
}

// ---------------- host ----------------
extern "C" void kernel_launch(void* const* d_in, const int* in_sizes, int n_in,
                              void* d_out, int out_size) {
    const float* Local = (const float*)d_in[0];
    const float* Remote = (const float*)d_in[1];
    const float *gWih0, *gWhh0, *gbih0, *gbhh0, *gWih1, *gWhh1, *gbih1, *gbhh1;
    const float *aew1, *aeb1, *aew2, *aeb2, *aeg, *aebt;
    const float *mdw1, *mdb1, *mdw2, *mdb2, *mdg, *mdbt;
    const float *mWih0, *mWhh0, *mbih0, *mbhh0, *mWih1, *mWhh1, *mbih1, *mbhh1;
#define FP(i) ((const float*)d_in[(i)])
    if (in_sizes[2] == 72) {
        gWih0 = FP(2); gWhh0 = FP(3); gbih0 = FP(4); gbhh0 = FP(5);
        gWih1 = FP(6); gWhh1 = FP(7); gbih1 = FP(8); gbhh1 = FP(9);
        int ae, m;
        if (in_sizes[10] == 16384) { ae = 10; m = 22; }   // signature order
        else                       { m = 10; ae = 18; }   // setup_inputs dict order
        aew1 = FP(ae + 0); aeb1 = FP(ae + 1); aew2 = FP(ae + 2);
        aeb2 = FP(ae + 3); aeg  = FP(ae + 4); aebt = FP(ae + 5);
        mdw1 = FP(ae + 6); mdb1 = FP(ae + 7); mdw2 = FP(ae + 8);
        mdb2 = FP(ae + 9); mdg  = FP(ae + 10); mdbt = FP(ae + 11);
        mWih0 = FP(m + 0); mWhh0 = FP(m + 1); mbih0 = FP(m + 2); mbhh0 = FP(m + 3);
        mWih1 = FP(m + 4); mWhh1 = FP(m + 5); mbih1 = FP(m + 6); mbhh1 = FP(m + 7);
    } else {
        // alphabetical fallback
        aeb1 = FP(2); aeb2 = FP(3); aebt = FP(4); aeg = FP(5); aew1 = FP(6); aew2 = FP(7);
        gWhh0 = FP(8); gWhh1 = FP(9); gWih0 = FP(10); gWih1 = FP(11);
        gbhh0 = FP(12); gbhh1 = FP(13); gbih0 = FP(14); gbih1 = FP(15);
        mWhh0 = FP(16); mWhh1 = FP(17); mWih0 = FP(18); mWih1 = FP(19);
        mbhh0 = FP(20); mbhh1 = FP(21); mbih0 = FP(22); mbih1 = FP(23);
        mdb1 = FP(24); mdb2 = FP(25); mdbt = FP(26); mdg = FP(27); mdw1 = FP(28); mdw2 = FP(29);
    }
#undef FP
    float* out = (float*)d_out;

    mega_kernel<<<528, 128>>>(Local, Remote, gWih0, gWhh0, gbih0, gbhh0,
                              gWih1, gWhh1, gbih1, gbhh1, aew1, aeb1);
    combine_kernel<<<512, 128>>>(aeg, aebt);
    fuse2_kernel<<<256, 128>>>(aew2, aeb2, mWih0, mbih0);
    mgru_kernel<<<64, 32>>>(mWhh0, mbhh0, mWih1, mbih1, mWhh1, mbhh1);
    dec1_kernel<<<1, 256>>>(Remote, mdw1, mdb1, mdg, mdbt);
    dec2_kernel<<<64, 128>>>(mdw2, mdb2, out);
}

// round 13
// speedup vs baseline: 1.1126x; 1.1126x over previous
#include <cuda_runtime.h>

#define FULL 0xffffffffu
#define BNEPS 1e-5f

// ---------------- scratch (device globals; allocation is forbidden) ----------------
__device__ float d_gate[2][64][128][8];   // softmax gates (side, b, t, e)
__device__ float d_y[2][8192][128];       // ungated expert layer-1 outputs [n][e*16+hh]
__device__ float d_hpre[2][8192][16];     // gated expert layer-1 hidden (pre-BN)
__device__ float d_part[2][256][32];      // per-block BN partials [sum(16) | sumsq(16)]
__device__ float d_bn[2][2][16];          // per-side BN scale/shift
__device__ float d_xw0[8192][48];         // precomputed main-GRU layer0 input projection
__device__ float d_Zlast[64][16];         // main GRU final hidden
__device__ float d_q[64][128];            // decoder gated hidden
__device__ unsigned int d_cnt;            // combine completion counter (self-resetting)

// ---------------- fast math ----------------
__device__ __forceinline__ float tanha(float x) {
    float y;
    asm("tanh.approx.f32 %0, %1;" : "=f"(y) : "f"(x));
    return y;
}
__device__ __forceinline__ float sigt(float x) {          // sigmoid via tanh
    return fmaf(tanha(0.5f * x), 0.5f, 0.5f);
}
typedef unsigned long long ull;
__device__ __forceinline__ ull pack2(float x, float y) {
    ull r;
    asm("mov.b64 %0, {%1, %2};" : "=l"(r) : "f"(x), "f"(y));
    return r;
}
__device__ __forceinline__ void unpack2(ull v, float& x, float& y) {
    asm("mov.b64 {%0, %1}, %2;" : "=f"(x), "=f"(y) : "l"(v));
}
__device__ __forceinline__ ull fma2(ull a, ull b, ull c) {
    ull d;
    asm("fma.rn.f32x2 %0, %1, %2, %3;" : "=l"(d) : "l"(a), "l"(b), "l"(c));
    return d;
}
__device__ __forceinline__ ull add2(ull a, ull b) {
    ull d;
    asm("add.rn.f32x2 %0, %1, %2;" : "=l"(d) : "l"(a), "l"(b));
    return d;
}
// packed dot over 8 floats (4 pairs) with packed bias (bias in lo half)
__device__ __forceinline__ float dot8p(const ull* w, const ull* h, ull bias2) {
    ull a0 = fma2(w[0], h[0], bias2);
    ull a1 = fma2(w[1], h[1], 0ull);
    a0 = fma2(w[2], h[2], a0);
    a1 = fma2(w[3], h[3], a1);
    ull s = add2(a0, a1);
    float lo, hi; unpack2(s, lo, hi);
    return lo + hi;
}
// packed dot over 16 floats (8 pairs) with packed bias
__device__ __forceinline__ float dot16p(const ull* w, const ull* h, ull bias2) {
    ull a0 = fma2(w[0], h[0], bias2);
    ull a1 = fma2(w[1], h[1], 0ull);
    a0 = fma2(w[2], h[2], a0);
    a1 = fma2(w[3], h[3], a1);
    a0 = fma2(w[4], h[4], a0);
    a1 = fma2(w[5], h[5], a1);
    a0 = fma2(w[6], h[6], a0);
    a1 = fma2(w[7], h[7], a1);
    ull s = add2(a0, a1);
    float lo, hi; unpack2(s, lo, hi);
    return lo + hi;
}
__device__ __forceinline__ void loadpack(ull* dst, const float* src, int npairs) {
#pragma unroll
    for (int k = 0; k < 8; k++) {
        if (k < npairs) {
            float2 v = *(const float2*)(src + 2 * k);
            dst[k] = pack2(v.x, v.y);
        }
    }
}
__device__ __forceinline__ void lds4(ull* h, const float* hsrc) {
    ulonglong2 q0 = *(const ulonglong2*)hsrc;
    ulonglong2 q1 = *(const ulonglong2*)(hsrc + 4);
    h[0] = q0.x; h[1] = q0.y; h[2] = q1.x; h[3] = q1.y;
}
__device__ __forceinline__ void lds8(ull* h, const float* hsrc) {
    lds4(h, hsrc);
    lds4(h + 4, hsrc + 8);
}

// ---------------- K1 mega: blocks 0-15 = gate GRU; blocks 16-527 = ungated expert GEMM ----------------
__global__ void __launch_bounds__(128) mega_kernel(
    const float* __restrict__ Local, const float* __restrict__ Remote,
    const float* __restrict__ Wih0, const float* __restrict__ Whh0,
    const float* __restrict__ bih0, const float* __restrict__ bhh0,
    const float* __restrict__ Wih1, const float* __restrict__ Whh1,
    const float* __restrict__ bih1, const float* __restrict__ bhh1,
    const float* __restrict__ w1, const float* __restrict__ b1)
{
    __shared__ __align__(16) float2 xs2[4][8][128];

    if (blockIdx.x < 16) {
        // ================= gate GRU (packed math, smem broadcast, branch-free loop) =================
        __shared__ __align__(16) float gb[4][2][2][16];  // [warp][layer][buf][2 sides x 8]
        int w = threadIdx.x >> 5;
        int b = blockIdx.x * 4 + w;                       // 0..63
        int lane = threadIdx.x & 31;
        int sub = (lane >> 3) & 1;                        // lanes 16-31 duplicate 0-15
        int j = lane & 7;
        int r1r = 8 + j, r1n = 16 + j;

        float wir[3], wiz[3], win[3];
#pragma unroll
        for (int k = 0; k < 3; k++) {
            wir[k] = Wih0[j * 3 + k];
            wiz[k] = Wih0[r1r * 3 + k];
            win[k] = Wih0[r1n * 3 + k];
        }
        float bir = bih0[j], biz = bih0[r1r], bin = bih0[r1n];
        ull whr2[4], whz2[4], whn2[4], wir12[4], wiz12[4], win12[4],
            whr12[4], whz12[4], whn12[4];
        loadpack(whr2, Whh0 + j * 8, 4);   loadpack(whz2, Whh0 + r1r * 8, 4);
        loadpack(whn2, Whh0 + r1n * 8, 4);
        loadpack(wir12, Wih1 + j * 8, 4);  loadpack(wiz12, Wih1 + r1r * 8, 4);
        loadpack(win12, Wih1 + r1n * 8, 4);
        loadpack(whr12, Whh1 + j * 8, 4);  loadpack(whz12, Whh1 + r1r * 8, 4);
        loadpack(whn12, Whh1 + r1n * 8, 4);
        ull bhr2 = pack2(bhh0[j], 0.f), bhz2 = pack2(bhh0[r1r], 0.f), bhn2 = pack2(bhh0[r1n], 0.f);
        ull bir12 = pack2(bih1[j], 0.f), biz12 = pack2(bih1[r1r], 0.f), bin12 = pack2(bih1[r1n], 0.f);
        ull bhr12 = pack2(bhh1[j], 0.f), bhz12 = pack2(bhh1[r1r], 0.f), bhn12 = pack2(bhh1[r1n], 0.f);

        ull h0p[4], h1p[4];
#pragma unroll
        for (int k = 0; k < 4; k++) { h0p[k] = 0ull; h1p[k] = 0ull; }
        float own0 = 0.f, own1 = 0.f;

        const float* xb = (sub ? Remote : Local) + (size_t)b * 16896 + 128;
        float* outp = &d_gate[sub][b][0][0];
        float4 xc = *(const float4*)xb;

        for (int t = 0; t < 128; t++) {
            int tn = (t < 127) ? (t + 1) : 127;           // clamp -> unconditional LDG
            float4 xn = *(const float4*)(xb + (size_t)tn * 132);
            int buf = t & 1;
            // ---- layer 0 ----
            float xwr = fmaf(xc.z, wir[2], fmaf(xc.y, wir[1], fmaf(xc.x, wir[0], bir)));
            float xwz = fmaf(xc.z, wiz[2], fmaf(xc.y, wiz[1], fmaf(xc.x, wiz[0], biz)));
            float xwn = fmaf(xc.z, win[2], fmaf(xc.y, win[1], fmaf(xc.x, win[0], bin)));
            float ghr = dot8p(whr2, h0p, bhr2);
            float ghz = dot8p(whz2, h0p, bhz2);
            float ghn = dot8p(whn2, h0p, bhn2);
            float r = sigt(xwr + ghr);
            float z = sigt(xwz + ghz);
            float n = tanha(fmaf(r, ghn, xwn));
            float hn = fmaf(z, own0 - n, n);
            own0 = hn;
            gb[w][0][buf][sub * 8 + j] = hn;   // lanes 16-31 duplicate same value
            __syncwarp();
            lds4(h0p, &gb[w][0][buf][sub * 8]);
            // ---- layer 1 ----
            float xwr1 = dot8p(wir12, h0p, bir12);
            float xwz1 = dot8p(wiz12, h0p, biz12);
            float xwn1 = dot8p(win12, h0p, bin12);
            float ghr1 = dot8p(whr12, h1p, bhr12);
            float ghz1 = dot8p(whz12, h1p, bhz12);
            float ghn1 = dot8p(whn12, h1p, bhn12);
            float rr1 = sigt(xwr1 + ghr1);
            float zz1 = sigt(xwz1 + ghz1);
            float nn1 = tanha(fmaf(rr1, ghn1, xwn1));
            float hn1 = fmaf(zz1, own1 - nn1, nn1);
            own1 = hn1;
            gb[w][1][buf][sub * 8 + j] = hn1;
            __syncwarp();
            lds4(h1p, &gb[w][1][buf][sub * 8]);
            // ---- softmax over 8 (h1 in (-1,1): no max shift) ----
            float ev = __expf(hn1);
            float ss = ev;
            ss += __shfl_xor_sync(FULL, ss, 1);
            ss += __shfl_xor_sync(FULL, ss, 2);
            ss += __shfl_xor_sync(FULL, ss, 4);
            outp[t * 8 + j] = __fdividef(ev, ss);   // lanes 16-31 store identical bytes
            xc = xn;
        }
    } else {
        // ================= ungated expert layer-1 GEMM =================
        int bx = blockIdx.x - 16;          // 0..511
        int side = bx >> 8;
        int bq = bx & 255;
        const float* src = side ? Remote : Local;
        int w = threadIdx.x >> 5, lane = threadIdx.x & 31;
        int n0 = bq * 32 + w * 8;

#pragma unroll
        for (int s = 0; s < 8; s++) {
            int n = n0 + s;
            int bb = n >> 7, t = n & 127;
            float4 v = *(const float4*)(src + (size_t)bb * 16896 + t * 132 + lane * 4);
            xs2[w][s][lane * 4 + 0] = make_float2(v.x, v.x);
            xs2[w][s][lane * 4 + 1] = make_float2(v.y, v.y);
            xs2[w][s][lane * 4 + 2] = make_float2(v.z, v.z);
            xs2[w][s][lane * 4 + 3] = make_float2(v.w, v.w);
        }
        int e = lane >> 2, hq = lane & 3;
        __syncthreads();

        ull a01[8], a23[8];
#pragma unroll
        for (int s = 0; s < 8; s++) { a01[s] = 0ull; a23[s] = 0ull; }

        const float* wbase = w1 + (size_t)e * 2048 + hq * 4;   // (e*128+i)*16 + 4*hq
#pragma unroll 4
        for (int i = 0; i < 128; i++) {
            float4 wv = *(const float4*)(wbase + i * 16);
            ull w01 = pack2(wv.x, wv.y);
            ull w23 = pack2(wv.z, wv.w);
#pragma unroll
            for (int s = 0; s < 8; s++) {
                ull xp = *(const ull*)&xs2[w][s][i];
                a01[s] = fma2(w01, xp, a01[s]);
                a23[s] = fma2(w23, xp, a23[s]);
            }
        }
        float4 bq4 = *(const float4*)(b1 + e * 16 + hq * 4);
#pragma unroll
        for (int s = 0; s < 8; s++) {
            float v0, v1, v2, v3;
            unpack2(a01[s], v0, v1);
            unpack2(a23[s], v2, v3);
            *(float4*)&d_y[side][n0 + s][lane * 4] =
                make_float4(v0 + bq4.x, v1 + bq4.y, v2 + bq4.z, v3 + bq4.w);
        }
    }
}

// ---------------- K2: gates -> hpre + BN partials; last block finalizes BN ----------------
__global__ void __launch_bounds__(128) combine_kernel(
    const float* __restrict__ ae_g, const float* __restrict__ ae_bt)
{
    __shared__ __align__(16) float ys[32][128];
    __shared__ float gs[32][8];
    __shared__ float hsm[32][16];
    __shared__ float sred[128];
    __shared__ float stot[2][32];
    __shared__ int lastflag;
    int t = threadIdx.x;
    int blk = blockIdx.x;                 // 0..511
    int side = blk >> 8;
    int grp = blk & 255;
    int n0 = grp * 32;
    const float* gp = &d_gate[0][0][0][0];

#pragma unroll
    for (int i = 0; i < 8; i++) {
        int idx = i * 128 + t;            // 1024 float4
        int s = idx >> 5, c = idx & 31;
        ((float4*)&ys[s][0])[c] = ((const float4*)&d_y[side][n0 + s][0])[c];
    }
#pragma unroll
    for (int i = 0; i < 2; i++) {
        int idx = i * 128 + t;            // 256 gates
        int s = idx >> 3, e = idx & 7;
        gs[s][e] = gp[((size_t)side * 8192 + n0 + s) * 8 + e];
    }
    __syncthreads();
    {
        int s = t >> 2, q = t & 3;
        float4 acc = {0.f, 0.f, 0.f, 0.f};
#pragma unroll
        for (int e = 0; e < 8; e++) {
            float g = gs[s][e];
            float4 y4 = *(const float4*)&ys[s][e * 16 + q * 4];
            acc.x = fmaf(g, y4.x, acc.x); acc.y = fmaf(g, y4.y, acc.y);
            acc.z = fmaf(g, y4.z, acc.z); acc.w = fmaf(g, y4.w, acc.w);
        }
        *(float4*)&d_hpre[side][n0 + s][q * 4] = acc;
        *(float4*)&hsm[s][q * 4] = acc;
    }
    __syncthreads();
    if (t < 32) {
        int c = t & 15, kind = t >> 4;
        float a = 0.f;
#pragma unroll 8
        for (int ss = 0; ss < 32; ss++) {
            float v = hsm[ss][c];
            a += kind ? v * v : v;
        }
        d_part[side][grp][t] = a;
    }
    // ---- last-block BN finalize ----
    __threadfence();
    __syncthreads();
    if (t == 0) {
        unsigned int v = atomicAdd(&d_cnt, 1u);
        lastflag = (v == 511u);
    }
    __syncthreads();
    if (lastflag) {
        int sd = t >> 6, rem = t & 63;
        int c = rem & 31, half = rem >> 5;
        float a = 0.f;
#pragma unroll 8
        for (int k = 0; k < 128; k++) a += d_part[sd][half * 128 + k][c];
        sred[t] = a;
        __syncthreads();
        if (t < 64) {
            int s2 = t >> 5, c2 = t & 31;
            stot[s2][c2] = sred[s2 * 64 + c2] + sred[s2 * 64 + 32 + c2];
        }
        __syncthreads();
        if (t < 32) {
            int s2 = t >> 4, ch = t & 15;
            float m = stot[s2][ch] * (1.f / 8192.f);
            float vv = stot[s2][16 + ch] * (1.f / 8192.f) - m * m;
            float a2 = ae_g[ch] * rsqrtf(vv + BNEPS);
            d_bn[s2][0][ch] = a2;
            d_bn[s2][1][ch] = ae_bt[ch] - m * a2;
        }
        if (t == 0) d_cnt = 0u;          // reset for next graph replay
    }
}

// ---------------- K3: fused BN+ELU + gated-combine GEMM + projection ----------------
__global__ void __launch_bounds__(128) fuse2_kernel(
    const float* __restrict__ w2, const float* __restrict__ b2,
    const float* __restrict__ mWih0, const float* __restrict__ mbih0)
{
    __shared__ float sh[32][33];          // ELU'd hidden: [s][0..15]=L, [16..31]=R
    __shared__ __align__(16) float hg[32][132];
    __shared__ __align__(16) float w2t[16][132];   // transposed w2: [o][k]
    __shared__ float b2s[128];
    __shared__ float gl[32][8], gr[32][8];
    __shared__ float zs[32][17];
    __shared__ __align__(16) float mWs[768];
    __shared__ float mbs[48];
    int t = threadIdx.x;
    int n0 = blockIdx.x * 32;
    const float* gp = &d_gate[0][0][0][0];

#pragma unroll
    for (int i = 0; i < 16; i++) {
        int idx = i * 128 + t;           // 2048
        int o = idx >> 7, k = idx & 127;
        w2t[o][k] = w2[k * 16 + o];
    }
    b2s[t] = b2[t];
#pragma unroll
    for (int i = 0; i < 6; i++) mWs[i * 128 + t] = mWih0[i * 128 + t];
    if (t < 48) mbs[t] = mbih0[t];
#pragma unroll
    for (int i = 0; i < 4; i++) {
        int idx = i * 128 + t;           // 512 = 32 samples x 16 gates
        int s = idx >> 4, c = idx & 15;
        float v = gp[((size_t)((c >> 3) * 8192) + n0 + s) * 8 + (c & 7)];
        if (c < 8) gl[s][c] = v; else gr[s][c - 8] = v;
    }
#pragma unroll
    for (int i = 0; i < 8; i++) {
        int idx = i * 128 + t;           // 1024 = 32 x 32
        int s = idx >> 5, c = idx & 31;
        int side = c >> 4, ch = c & 15;
        float a = d_bn[side][0][ch] * d_hpre[side][n0 + s][ch] + d_bn[side][1][ch];
        sh[s][c] = a > 0.f ? a : (__expf(a) - 1.f);
    }
    __syncthreads();
    {
        int e = t >> 4, hh = t & 15;
#pragma unroll 4
        for (int s = 0; s < 32; s++)
            hg[s][t] = fmaf(gl[s][e], sh[s][hh], gr[s][e] * sh[s][16 + hh]);
    }
    __syncthreads();
    {
        int o = t & 15, sg = t >> 4;      // sg 0..7, 4 samples each
        int s0 = sg * 4;
        float a0 = 0.f, a1 = 0.f, a2 = 0.f, a3 = 0.f;
#pragma unroll 4
        for (int k = 0; k < 128; k += 4) {
            float4 wv = *(const float4*)&w2t[o][k];
            float4 g0 = *(const float4*)&hg[s0 + 0][k];
            float4 g1 = *(const float4*)&hg[s0 + 1][k];
            float4 g2 = *(const float4*)&hg[s0 + 2][k];
            float4 g3 = *(const float4*)&hg[s0 + 3][k];
            a0 = fmaf(g0.x, wv.x, a0); a0 = fmaf(g0.y, wv.y, a0);
            a0 = fmaf(g0.z, wv.z, a0); a0 = fmaf(g0.w, wv.w, a0);
            a1 = fmaf(g1.x, wv.x, a1); a1 = fmaf(g1.y, wv.y, a1);
            a1 = fmaf(g1.z, wv.z, a1); a1 = fmaf(g1.w, wv.w, a1);
            a2 = fmaf(g2.x, wv.x, a2); a2 = fmaf(g2.y, wv.y, a2);
            a2 = fmaf(g2.z, wv.z, a2); a2 = fmaf(g2.w, wv.w, a2);
            a3 = fmaf(g3.x, wv.x, a3); a3 = fmaf(g3.y, wv.y, a3);
            a3 = fmaf(g3.z, wv.z, a3); a3 = fmaf(g3.w, wv.w, a3);
        }
        float accs[4] = {a0, a1, a2, a3};
#pragma unroll
        for (int ss = 0; ss < 4; ss++) {
            float bsum = accs[ss];
#pragma unroll
            for (int e = 0; e < 8; e++)
                bsum = fmaf(gl[s0 + ss][e] + gr[s0 + ss][e], b2s[e * 16 + o], bsum);
            zs[s0 + ss][o] = bsum;
        }
    }
    __syncthreads();
    {
        int s = t >> 2, q = t & 3;        // 12 outputs per thread
        float z[16];
#pragma unroll
        for (int h = 0; h < 16; h++) z[h] = zs[s][h];
#pragma unroll
        for (int gi = 0; gi < 12; gi++) {
            int g = q * 12 + gi;
            float acc = mbs[g];
#pragma unroll
            for (int h = 0; h < 16; h++) acc = fmaf(z[h], mWs[g * 16 + h], acc);
            d_xw0[n0 + s][g] = acc;
        }
    }
}

// ---------------- K4: main GRU — packed math, smem broadcast, branch-free loop ----------------
// 1 warp per sample; lanes 0-15: r+n rows, lanes 16-31: z row
__global__ void __launch_bounds__(32) mgru_kernel(
    const float* __restrict__ Whh0, const float* __restrict__ bhh0_,
    const float* __restrict__ Wih1, const float* __restrict__ bih1_,
    const float* __restrict__ Whh1, const float* __restrict__ bhh1_)
{
    __shared__ __align__(16) float hs[2][2][32];    // [layer][buf][32] (16 live + 16 pad)
    int b = blockIdx.x;
    int lane = threadIdx.x;
    int j = lane & 15;
    int rowA = (lane < 16) ? j : 16 + j;   // r (lanes<16) or z (lanes>=16)
    int rowB = 32 + j;                     // n row (lanes<16)

    ull whA2[8], whB2[8], wiA12[8], wiB12[8], whA12[8], whB12[8];
    loadpack(whA2, Whh0 + rowA * 16, 8);
    loadpack(whB2, Whh0 + rowB * 16, 8);
    loadpack(wiA12, Wih1 + rowA * 16, 8);
    loadpack(wiB12, Wih1 + rowB * 16, 8);
    loadpack(whA12, Whh1 + rowA * 16, 8);
    loadpack(whB12, Whh1 + rowB * 16, 8);
    ull bhA2 = pack2(bhh0_[rowA], 0.f), bhB2 = pack2(bhh0_[rowB], 0.f);
    ull biA2 = pack2(bih1_[rowA], 0.f), biB2 = pack2(bih1_[rowB], 0.f);
    ull bhA12 = pack2(bhh1_[rowA], 0.f), bhB12 = pack2(bhh1_[rowB], 0.f);

    ull h0p[8], h1p[8];
#pragma unroll
    for (int k = 0; k < 8; k++) { h0p[k] = 0ull; h1p[k] = 0ull; }
    float own0 = 0.f, own1 = 0.f;

    const float* xwp = &d_xw0[b * 128][0];
    float xwA = xwp[rowA], xwB = xwp[rowB];

    for (int t = 0; t < 128; t++) {
        int tn = (t < 127) ? (t + 1) : 127;            // clamp -> unconditional LDG
        float nxA = xwp[tn * 48 + rowA];
        float nxB = xwp[tn * 48 + rowB];
        int buf = t & 1;
        // ---- layer 0 ----
        float ghA = dot16p(whA2, h0p, bhA2);
        float s = sigt(xwA + ghA);                      // r (lanes<16) / z (lanes>=16)
        float ghB = dot16p(whB2, h0p, bhB2);
        float n = tanha(fmaf(s, ghB, xwB));             // lanes<16
        float z = __shfl_sync(FULL, s, 16 + j);
        float hn = fmaf(z, own0 - n, n);                // valid on lanes<16
        own0 = hn;
        hs[0][buf][lane] = hn;                          // unconditional; lanes 16-31 pad
        __syncwarp();
        lds8(h0p, &hs[0][buf][0]);
        // ---- layer 1 ----
        float xwA1 = dot16p(wiA12, h0p, biA2);
        float ghA1 = dot16p(whA12, h1p, bhA12);
        float s1 = sigt(xwA1 + ghA1);
        float xwB1 = dot16p(wiB12, h0p, biB2);
        float ghB1 = dot16p(whB12, h1p, bhB12);
        float n1 = tanha(fmaf(s1, ghB1, xwB1));
        float z1 = __shfl_sync(FULL, s1, 16 + j);
        float hn1 = fmaf(z1, own1 - n1, n1);
        own1 = hn1;
        hs[1][buf][lane] = hn1;                         // unconditional; lanes 16-31 pad
        __syncwarp();
        lds8(h1p, &hs[1][buf][0]);
        xwA = nxA; xwB = nxB;
    }
    if (lane < 16) d_Zlast[b][j] = own1;
}

// ---------------- K5: decoder expert layer-1 + BN + ELU + gate-weighting ----------------
__global__ void __launch_bounds__(256) dec1_kernel(
    const float* __restrict__ Remote,
    const float* __restrict__ w1, const float* __restrict__ b1,
    const float* __restrict__ gmd, const float* __restrict__ btmd)
{
    __shared__ float w1s[2176];
    __shared__ float sb1[128];
    __shared__ float sh[64][17];
    __shared__ float sa[16], sc[16];
    int tid = threadIdx.x;
    for (int i = tid; i < 2176; i += 256) w1s[i] = w1[i];
    if (tid < 128) sb1[tid] = b1[tid];
    int b = tid >> 2, q = tid & 3;
    float x[17];
#pragma unroll
    for (int k = 0; k < 16; k++) x[k] = d_Zlast[b][k];
    x[16] = Remote[(size_t)b * 16896 + 127 * 132 + 131];
    const float* gp = &d_gate[0][0][0][0];
    float om[8];
#pragma unroll
    for (int e = 0; e < 8; e++) om[e] = gp[(size_t)(8192 + b * 128 + 127) * 8 + e];
    __syncthreads();
    float h[4];
#pragma unroll
    for (int hq = 0; hq < 4; hq++) {
        int hh = q * 4 + hq;
        float acc = 0.f;
#pragma unroll 1
        for (int e = 0; e < 8; e++) {
            float a = sb1[e * 16 + hh];
#pragma unroll
            for (int i = 0; i < 17; i++) a = fmaf(x[i], w1s[e * 272 + i * 16 + hh], a);
            acc = fmaf(om[e], a, acc);
        }
        h[hq] = acc;
        sh[b][hh] = acc;
    }
    __syncthreads();
    if (tid < 16) {
        float s = 0.f, s2 = 0.f;
#pragma unroll 8
        for (int bb = 0; bb < 64; bb++) {
            float v = sh[bb][tid];
            s += v; s2 = fmaf(v, v, s2);
        }
        float m = s * (1.f / 64.f);
        float vv = s2 * (1.f / 64.f) - m * m;
        float a = gmd[tid] * rsqrtf(vv + BNEPS);
        sa[tid] = a;
        sc[tid] = btmd[tid] - m * a;
    }
    __syncthreads();
#pragma unroll
    for (int hq = 0; hq < 4; hq++) {
        int hh = q * 4 + hq;
        float t = sa[hh] * h[hq] + sc[hh];
        float hv = t > 0.f ? t : (__expf(t) - 1.f);
#pragma unroll
        for (int e = 0; e < 8; e++) d_q[b][e * 16 + hh] = om[e] * hv;
    }
}

// ---------------- K6: decoder layer-2 -> output ----------------
__global__ void __launch_bounds__(128) dec2_kernel(
    const float* __restrict__ w2, const float* __restrict__ b2,
    float* __restrict__ out)
{
    int b = blockIdx.x, o = threadIdx.x;
    __shared__ float sq[128];
    sq[o] = d_q[b][o];
    __syncthreads();
    const float* gp = &d_gate[0][0][0][0];
    float acc = 0.f;
#pragma unroll 4
    for (int k = 0; k < 128; k++) acc = fmaf(sq[k], w2[k * 128 + o], acc);
#pragma unroll
    for (int e = 0; e < 8; e++)
        acc = fmaf(gp[(size_t)(8192 + b * 128 + 127) * 8 + e], b2[e * 128 + o], acc);
    out[b * 128 + o] = acc;
}

// ---------------- host ----------------
extern "C" void kernel_launch(void* const* d_in, const int* in_sizes, int n_in,
                              void* d_out, int out_size) {
    const float* Local = (const float*)d_in[0];
    const float* Remote = (const float*)d_in[1];
    const float *gWih0, *gWhh0, *gbih0, *gbhh0, *gWih1, *gWhh1, *gbih1, *gbhh1;
    const float *aew1, *aeb1, *aew2, *aeb2, *aeg, *aebt;
    const float *mdw1, *mdb1, *mdw2, *mdb2, *mdg, *mdbt;
    const float *mWih0, *mWhh0, *mbih0, *mbhh0, *mWih1, *mWhh1, *mbih1, *mbhh1;
#define FP(i) ((const float*)d_in[(i)])
    if (in_sizes[2] == 72) {
        gWih0 = FP(2); gWhh0 = FP(3); gbih0 = FP(4); gbhh0 = FP(5);
        gWih1 = FP(6); gWhh1 = FP(7); gbih1 = FP(8); gbhh1 = FP(9);
        int ae, m;
        if (in_sizes[10] == 16384) { ae = 10; m = 22; }   // signature order
        else                       { m = 10; ae = 18; }   // setup_inputs dict order
        aew1 = FP(ae + 0); aeb1 = FP(ae + 1); aew2 = FP(ae + 2);
        aeb2 = FP(ae + 3); aeg  = FP(ae + 4); aebt = FP(ae + 5);
        mdw1 = FP(ae + 6); mdb1 = FP(ae + 7); mdw2 = FP(ae + 8);
        mdb2 = FP(ae + 9); mdg  = FP(ae + 10); mdbt = FP(ae + 11);
        mWih0 = FP(m + 0); mWhh0 = FP(m + 1); mbih0 = FP(m + 2); mbhh0 = FP(m + 3);
        mWih1 = FP(m + 4); mWhh1 = FP(m + 5); mbih1 = FP(m + 6); mbhh1 = FP(m + 7);
    } else {
        // alphabetical fallback
        aeb1 = FP(2); aeb2 = FP(3); aebt = FP(4); aeg = FP(5); aew1 = FP(6); aew2 = FP(7);
        gWhh0 = FP(8); gWhh1 = FP(9); gWih0 = FP(10); gWih1 = FP(11);
        gbhh0 = FP(12); gbhh1 = FP(13); gbih0 = FP(14); gbih1 = FP(15);
        mWhh0 = FP(16); mWhh1 = FP(17); mWih0 = FP(18); mWih1 = FP(19);
        mbhh0 = FP(20); mbhh1 = FP(21); mbih0 = FP(22); mbih1 = FP(23);
        mdb1 = FP(24); mdb2 = FP(25); mdbt = FP(26); mdg = FP(27); mdw1 = FP(28); mdw2 = FP(29);
    }
#undef FP
    float* out = (float*)d_out;

    mega_kernel<<<528, 128>>>(Local, Remote, gWih0, gWhh0, gbih0, gbhh0,
                              gWih1, gWhh1, gbih1, gbhh1, aew1, aeb1);
    combine_kernel<<<512, 128>>>(aeg, aebt);
    fuse2_kernel<<<256, 128>>>(aew2, aeb2, mWih0, mbih0);
    mgru_kernel<<<64, 32>>>(mWhh0, mbhh0, mWih1, mbih1, mWhh1, mbhh1);
    dec1_kernel<<<1, 256>>>(Remote, mdw1, mdb1, mdg, mdbt);
    dec2_kernel<<<64, 128>>>(mdw2, mdb2, out);
}